// round 4
// baseline (speedup 1.0000x reference)
#include <cuda_runtime.h>
#include <cuda_bf16.h>

// Problem constants
#define GR      64                 // grid resolution per axis
#define NB      8                  // batch
#define NP      4096               // points per batch
#define CHUNK   64                 // points per block
#define NCH     (NP / CHUNK)       // 64 chunks per batch
#define GG      (GR * GR)          // 4096 grid points

// Partial accumulators: [b][chunk][3][GG]  -> 8*64*3*4096 floats = 25.2 MB (L2-resident)
__device__ float g_partial[NB * NCH * 3 * GG];

// Kernel 1: per (batch, point-chunk) block, compute separable Gaussian factors
//   U[n][gx] = mask_n * exp(-50*(x0_n - cx[gx])^2)
//   V[n][gy] =          exp(-50*(x1_n - cy[gy])^2)
// then accumulate partial sums over the chunk:
//   d[gy][gx]  += V*U ;  s0 += y_n*V*U ;  s1 += t_n*V*U
__global__ __launch_bounds__(256)
void rbf_partial_kernel(const float* __restrict__ x_c,
                        const float* __restrict__ y_c,
                        const float* __restrict__ t_c,
                        const int*   __restrict__ mask)
{
    __shared__ float Ush[CHUNK * 64];   // 16 KB
    __shared__ float Vsh[CHUNK * 64];   // 16 KB
    __shared__ float ysh[CHUNK], tsh[CHUNK];
    __shared__ float x0s[CHUNK], x1s[CHUNK], msh[CHUNK];

    const int ch  = blockIdx.x;         // 0..NCH-1
    const int b   = blockIdx.y;         // 0..NB-1
    const int tid = threadIdx.x;        // 0..255
    const int base = b * NP + ch * CHUNK;

    // ---- load point data for this chunk ----
    if (tid < CHUNK) {
        int n = base + tid;
        x0s[tid] = x_c[2 * n + 0];
        x1s[tid] = x_c[2 * n + 1];
        ysh[tid] = y_c[n];
        tsh[tid] = t_c[n];
        msh[tid] = (mask[n] != 0) ? 0.0f : 1.0f;   // nonzero = drop point
    }
    __syncthreads();

    // ---- Phase A: build U, V in shared ----
    // thread -> (g = tid&63, i0 = tid>>6); warp writes 32 consecutive g -> conflict-free
    {
        const int g  = tid & 63;
        const int i0 = tid >> 6;                       // 0..3
        const float cg = -1.0f + (float)g * (2.0f / 63.0f);
        #pragma unroll
        for (int j = i0; j < CHUNK; j += 4) {
            float dx = x0s[j] - cg;
            float dy = x1s[j] - cg;
            Ush[j * 64 + g] = msh[j] * __expf(-50.0f * dx * dx);
            Vsh[j * 64 + g] =          __expf(-50.0f * dy * dy);
        }
    }
    __syncthreads();

    // ---- Phase B: rank-1 accumulation over the chunk ----
    // thread -> gy = tid>>2 (64 rows), gx block = (tid&3)*16 (4 float4 each)
    const int gy  = tid >> 2;
    const int gxg = tid & 3;

    float4 aD[4], aY[4], aT[4];
    #pragma unroll
    for (int k = 0; k < 4; k++) {
        aD[k] = make_float4(0.f, 0.f, 0.f, 0.f);
        aY[k] = make_float4(0.f, 0.f, 0.f, 0.f);
        aT[k] = make_float4(0.f, 0.f, 0.f, 0.f);
    }

    #pragma unroll 2
    for (int n = 0; n < CHUNK; n++) {
        const float v  = Vsh[n * 64 + gy];
        const float yn = ysh[n];
        const float tn = tsh[n];
        const float4* Urow = reinterpret_cast<const float4*>(Ush + n * 64) + gxg * 4;
        #pragma unroll
        for (int k = 0; k < 4; k++) {
            float4 u = Urow[k];
            float w;
            w = v * u.x; aD[k].x += w; aY[k].x = fmaf(yn, w, aY[k].x); aT[k].x = fmaf(tn, w, aT[k].x);
            w = v * u.y; aD[k].y += w; aY[k].y = fmaf(yn, w, aY[k].y); aT[k].y = fmaf(tn, w, aT[k].y);
            w = v * u.z; aD[k].z += w; aY[k].z = fmaf(yn, w, aY[k].z); aT[k].z = fmaf(tn, w, aT[k].z);
            w = v * u.w; aD[k].w += w; aY[k].w = fmaf(yn, w, aY[k].w); aT[k].w = fmaf(tn, w, aT[k].w);
        }
    }

    // ---- store partial tile: [b][ch][c][gy*64+gx], fully coalesced STG.128 ----
    float* outp = g_partial + (size_t)(b * NCH + ch) * 3 * GG;
    const int col = gy * 64 + gxg * 16;
    #pragma unroll
    for (int k = 0; k < 4; k++) {
        *reinterpret_cast<float4*>(outp +          col + 4 * k) = aD[k];
        *reinterpret_cast<float4*>(outp + GG     + col + 4 * k) = aY[k];
        *reinterpret_cast<float4*>(outp + 2 * GG + col + 4 * k) = aT[k];
    }
}

// Kernel 2: reduce chunk partials, normalize, write (B,3,64,64) output
__global__ __launch_bounds__(256)
void rbf_finalize_kernel(float* __restrict__ out)
{
    const int idx = blockIdx.x * blockDim.x + threadIdx.x;   // over NB*GG
    if (idx >= NB * GG) return;
    const int b = idx / GG;
    const int g = idx % GG;

    const float* p = g_partial + (size_t)b * NCH * 3 * GG;
    float d = 0.f, s0 = 0.f, s1 = 0.f;
    #pragma unroll 8
    for (int ch = 0; ch < NCH; ch++) {
        const float* q = p + (size_t)ch * 3 * GG;
        d  += q[g];
        s0 += q[GG + g];
        s1 += q[2 * GG + g];
    }
    float* o = out + (size_t)b * 3 * GG;
    const float inv = 1.0f / (d + 1e-5f);
    o[g]          = d;
    o[GG + g]     = s0 * inv;
    o[2 * GG + g] = s1 * inv;
}

extern "C" void kernel_launch(void* const* d_in, const int* in_sizes, int n_in,
                              void* d_out, int out_size)
{
    const float* x_c  = (const float*)d_in[0];   // (8,4096,2) float32
    const float* y_c  = (const float*)d_in[1];   // (8,4096,1) float32
    const float* t_c  = (const float*)d_in[2];   // (8,4096,1) float32
    const int*   mask = (const int*)d_in[3];     // (8,4096) bool -> int32
    float* out = (float*)d_out;                  // (8,3,64,64) float32

    dim3 grid1(NCH, NB);            // 64 x 8 = 512 blocks
    rbf_partial_kernel<<<grid1, 256>>>(x_c, y_c, t_c, mask);

    const int total = NB * GG;      // 32768
    rbf_finalize_kernel<<<(total + 255) / 256, 256>>>(out);
}

// round 5
// speedup vs baseline: 1.9446x; 1.9446x over previous
#include <cuda_runtime.h>
#include <cuda_bf16.h>

// Problem constants
#define GR      64                 // grid resolution per axis
#define NB      8                  // batch
#define NP      4096               // points per batch
#define CHUNK   64                 // points per sub-chunk (shared tile)
#define CPB     2                  // sub-chunks per block
#define NPART   (NP / (CHUNK*CPB)) // 32 partial tiles per batch
#define GG      (GR * GR)          // 4096 grid points

// Partial accumulators: [b][part][3][GG] -> 8*32*3*4096 floats = 12.6 MB (L2-resident)
__device__ float g_partial[NB * NPART * 3 * GG];

// ---------- f32x2 packed helpers (sm_103a FFMA2 path, PTX-only) ----------
__device__ __forceinline__ unsigned long long splat2(float a) {
    unsigned long long r;
    asm("mov.b64 %0, {%1, %1};" : "=l"(r) : "f"(a));
    return r;
}
__device__ __forceinline__ void unpack2(unsigned long long v, float& lo, float& hi) {
    asm("mov.b64 {%0, %1}, %2;" : "=f"(lo), "=f"(hi) : "l"(v));
}
__device__ __forceinline__ unsigned long long mul2(unsigned long long a, unsigned long long b) {
    unsigned long long r;
    asm("mul.rn.f32x2 %0, %1, %2;" : "=l"(r) : "l"(a), "l"(b));
    return r;
}
#define FMA2(acc, a, b) asm("fma.rn.f32x2 %0, %1, %2, %0;" : "+l"(acc) : "l"(a), "l"(b))

// Kernel 1: per (batch, 128-point group) block.
// Separable factors U[n][gx] = mask*exp(-50 (x0-cx)^2), V[n][gy] = exp(-50 (x1-cy)^2)
// Rank-1 accumulate d += V*U, s0 += y*V*U, s1 += t*V*U over 128 points.
// Thread tile: 4 gy (as 2 f32x2 lanes-pairs) x 4 gx. 256 thr = 16 gy-groups x 16 gx-groups.
__global__ __launch_bounds__(256)
void rbf_partial_kernel(const float* __restrict__ x_c,
                        const float* __restrict__ y_c,
                        const float* __restrict__ t_c,
                        const int*   __restrict__ mask)
{
    __shared__ float Ush[CHUNK * 64];   // 16 KB
    __shared__ float Vsh[CHUNK * 64];   // 16 KB
    __shared__ float ysh[CHUNK], tsh[CHUNK];
    __shared__ float x0s[CHUNK], x1s[CHUNK], msh[CHUNK];

    const int part = blockIdx.x;        // 0..NPART-1
    const int b    = blockIdx.y;        // 0..NB-1
    const int tid  = threadIdx.x;       // 0..255

    const int gyg = tid >> 4;           // 0..15 -> gy rows [gyg*4, gyg*4+4)
    const int gxg = tid & 15;           // 0..15 -> gx cols [gxg*4, gxg*4+4)

    // accumulators: [gx 0..3][gy-pair 0..1], lanes of f32x2 run over gy
    unsigned long long aD[4][2], aY[4][2], aT[4][2];
    #pragma unroll
    for (int i = 0; i < 4; i++)
        #pragma unroll
        for (int j = 0; j < 2; j++) { aD[i][j] = 0ull; aY[i][j] = 0ull; aT[i][j] = 0ull; }

    for (int c = 0; c < CPB; c++) {
        if (c) __syncthreads();         // protect smem from previous Phase B readers

        // ---- load point scalars for this sub-chunk ----
        const int base = b * NP + (part * CPB + c) * CHUNK;
        if (tid < CHUNK) {
            int n = base + tid;
            x0s[tid] = x_c[2 * n + 0];
            x1s[tid] = x_c[2 * n + 1];
            ysh[tid] = y_c[n];
            tsh[tid] = t_c[n];
            msh[tid] = (mask[n] != 0) ? 0.0f : 1.0f;   // nonzero = drop point
        }
        __syncthreads();

        // ---- Phase A: build U, V (warp writes 32 consecutive g -> conflict-free) ----
        {
            const int g  = tid & 63;
            const int i0 = tid >> 6;                       // 0..3
            const float cg = -1.0f + (float)g * (2.0f / 63.0f);
            #pragma unroll
            for (int j = i0; j < CHUNK; j += 4) {
                float dx = x0s[j] - cg;
                float dy = x1s[j] - cg;
                Ush[j * 64 + g] = msh[j] * __expf(-50.0f * dx * dx);
                Vsh[j * 64 + g] =          __expf(-50.0f * dy * dy);
            }
        }
        __syncthreads();

        // ---- Phase B: rank-1 accumulation, f32x2 packed over gy ----
        #pragma unroll 2
        for (int n = 0; n < CHUNK; n++) {
            // v pair-loads: {v(gy0),v(gy1)}, {v(gy2),v(gy3)} -- 1x LDS.128
            const ulonglong2 v2 =
                *reinterpret_cast<const ulonglong2*>(Vsh + n * 64 + gyg * 4);
            // u: 4 gx values -- 1x LDS.128
            const float4 u4 =
                *reinterpret_cast<const float4*>(Ush + n * 64 + gxg * 4);

            const unsigned long long yn2 = splat2(ysh[n]);
            const unsigned long long tn2 = splat2(tsh[n]);
            unsigned long long vv[2]  = { v2.x, v2.y };
            unsigned long long vy[2]  = { mul2(v2.x, yn2), mul2(v2.y, yn2) };
            unsigned long long vt[2]  = { mul2(v2.x, tn2), mul2(v2.y, tn2) };

            const float uarr[4] = { u4.x, u4.y, u4.z, u4.w };
            #pragma unroll
            for (int i = 0; i < 4; i++) {
                const unsigned long long us = splat2(uarr[i]);
                #pragma unroll
                for (int j = 0; j < 2; j++) {
                    FMA2(aD[i][j], us, vv[j]);
                    FMA2(aY[i][j], us, vy[j]);
                    FMA2(aT[i][j], us, vt[j]);
                }
            }
        }
    }

    // ---- store partial tile [b][part][c][gy*64+gx], coalesced STG.128 ----
    float* outp = g_partial + (size_t)(b * NPART + part) * 3 * GG;
    #pragma unroll
    for (int r = 0; r < 4; r++) {                 // gy row within tile
        const int j = r >> 1, hi = r & 1;
        float4 wD, wY, wT;
        float lo0, hi0;
        unpack2(aD[0][j], lo0, hi0); wD.x = hi ? hi0 : lo0;
        unpack2(aD[1][j], lo0, hi0); wD.y = hi ? hi0 : lo0;
        unpack2(aD[2][j], lo0, hi0); wD.z = hi ? hi0 : lo0;
        unpack2(aD[3][j], lo0, hi0); wD.w = hi ? hi0 : lo0;
        unpack2(aY[0][j], lo0, hi0); wY.x = hi ? hi0 : lo0;
        unpack2(aY[1][j], lo0, hi0); wY.y = hi ? hi0 : lo0;
        unpack2(aY[2][j], lo0, hi0); wY.z = hi ? hi0 : lo0;
        unpack2(aY[3][j], lo0, hi0); wY.w = hi ? hi0 : lo0;
        unpack2(aT[0][j], lo0, hi0); wT.x = hi ? hi0 : lo0;
        unpack2(aT[1][j], lo0, hi0); wT.y = hi ? hi0 : lo0;
        unpack2(aT[2][j], lo0, hi0); wT.z = hi ? hi0 : lo0;
        unpack2(aT[3][j], lo0, hi0); wT.w = hi ? hi0 : lo0;
        const int col = (gyg * 4 + r) * 64 + gxg * 4;
        *reinterpret_cast<float4*>(outp +          col) = wD;
        *reinterpret_cast<float4*>(outp + GG     + col) = wY;
        *reinterpret_cast<float4*>(outp + 2 * GG + col) = wT;
    }
}

// Kernel 2: reduce NPART partials with 4-way split-K across threads, normalize.
// grid 512 blocks (8 b x 64 g-blocks) x 256 threads (64 g x 4 splits).
__global__ __launch_bounds__(256)
void rbf_finalize_kernel(float* __restrict__ out)
{
    __shared__ float sD[256], s0[256], s1[256];

    const int b    = blockIdx.x >> 6;
    const int gblk = blockIdx.x & 63;
    const int tid  = threadIdx.x;
    const int gl   = tid & 63;          // g within block
    const int sp   = tid >> 6;          // split 0..3 -> 8 chunks each
    const int g    = gblk * 64 + gl;

    const float* p = g_partial + (size_t)b * NPART * 3 * GG;
    float d = 0.f, a0 = 0.f, a1 = 0.f;
    #pragma unroll
    for (int k = 0; k < NPART / 4; k++) {
        const float* q = p + (size_t)(sp * (NPART / 4) + k) * 3 * GG;
        d  += q[g];
        a0 += q[GG + g];
        a1 += q[2 * GG + g];
    }
    sD[tid] = d; s0[tid] = a0; s1[tid] = a1;
    __syncthreads();

    if (tid < 64) {
        float dd = sD[tid] + sD[tid + 64] + sD[tid + 128] + sD[tid + 192];
        float y  = s0[tid] + s0[tid + 64] + s0[tid + 128] + s0[tid + 192];
        float t  = s1[tid] + s1[tid + 64] + s1[tid + 128] + s1[tid + 192];
        float inv = 1.0f / (dd + 1e-5f);
        float* o = out + (size_t)b * 3 * GG;
        o[g]          = dd;
        o[GG + g]     = y * inv;
        o[2 * GG + g] = t * inv;
    }
}

extern "C" void kernel_launch(void* const* d_in, const int* in_sizes, int n_in,
                              void* d_out, int out_size)
{
    const float* x_c  = (const float*)d_in[0];   // (8,4096,2) float32
    const float* y_c  = (const float*)d_in[1];   // (8,4096,1) float32
    const float* t_c  = (const float*)d_in[2];   // (8,4096,1) float32
    const int*   mask = (const int*)d_in[3];     // (8,4096) bool -> int32
    float* out = (float*)d_out;                  // (8,3,64,64) float32

    dim3 grid1(NPART, NB);              // 32 x 8 = 256 blocks, 128 points each
    rbf_partial_kernel<<<grid1, 256>>>(x_c, y_c, t_c, mask);

    rbf_finalize_kernel<<<NB * 64, 256>>>(out);  // 512 blocks
}

// round 6
// speedup vs baseline: 1.9922x; 1.0245x over previous
#include <cuda_runtime.h>
#include <cuda_bf16.h>

// Problem constants
#define GR      64                 // grid resolution per axis
#define NB      8                  // batch
#define NP      4096               // points per batch
#define CHUNK   64                 // points per sub-chunk (shared tile)
#define CPB     2                  // sub-chunks per block
#define NPART   (NP / (CHUNK*CPB)) // 32 partial tiles per batch
#define GG      (GR * GR)          // 4096 grid points

// Partial accumulators: [b][part][3][GG] -> 8*32*3*4096 floats = 12.6 MB (L2-resident)
__device__ float g_partial[NB * NPART * 3 * GG];

// ---------- f32x2 packed helpers (sm_103a FFMA2 path, PTX-only) ----------
__device__ __forceinline__ unsigned long long splat2(float a) {
    unsigned long long r;
    asm("mov.b64 %0, {%1, %1};" : "=l"(r) : "f"(a));
    return r;
}
__device__ __forceinline__ void unpack2(unsigned long long v, float& lo, float& hi) {
    asm("mov.b64 {%0, %1}, %2;" : "=f"(lo), "=f"(hi) : "l"(v));
}
#define FMA2(acc, a, b) asm("fma.rn.f32x2 %0, %1, %2, %0;" : "+l"(acc) : "l"(a), "l"(b))

// Kernel 1: per (batch, 128-point group) block.
//   U[n][gx]  = mask_n * exp(-50 (x0-cx)^2)
//   V[n][gy]  = exp(-50 (x1-cy)^2);  VY = V*y_n ;  VT = V*t_n   (Phase A)
// Phase B: pure rank-1 FMA2:  d += u*v ; s0 += u*vy ; s1 += u*vt
// Thread tile: 4 gy (2 f32x2 pairs) x 4 gx.
extern __shared__ float dynsmem[];   // [U | V | VY | VT], 4 * 4096 floats = 64 KB

__global__ __launch_bounds__(256, 2)
void rbf_partial_kernel(const float* __restrict__ x_c,
                        const float* __restrict__ y_c,
                        const float* __restrict__ t_c,
                        const int*   __restrict__ mask)
{
    float* Ush  = dynsmem;                 // 64n x 64gx
    float* Vsh  = dynsmem + 1 * CHUNK * 64;
    float* VYsh = dynsmem + 2 * CHUNK * 64;
    float* VTsh = dynsmem + 3 * CHUNK * 64;

    __shared__ float ysh[CHUNK], tsh[CHUNK];
    __shared__ float x0s[CHUNK], x1s[CHUNK], msh[CHUNK];

    const int part = blockIdx.x;        // 0..NPART-1
    const int b    = blockIdx.y;        // 0..NB-1
    const int tid  = threadIdx.x;       // 0..255

    const int gyg = tid >> 4;           // 0..15 -> gy rows [gyg*4, gyg*4+4)
    const int gxg = tid & 15;           // 0..15 -> gx cols [gxg*4, gxg*4+4)

    // accumulators: [gx 0..3][gy-pair 0..1]
    unsigned long long aD[4][2], aY[4][2], aT[4][2];
    #pragma unroll
    for (int i = 0; i < 4; i++)
        #pragma unroll
        for (int j = 0; j < 2; j++) { aD[i][j] = 0ull; aY[i][j] = 0ull; aT[i][j] = 0ull; }

    for (int c = 0; c < CPB; c++) {
        if (c) __syncthreads();         // protect smem from previous Phase B readers

        // ---- load point scalars for this sub-chunk ----
        const int base = b * NP + (part * CPB + c) * CHUNK;
        if (tid < CHUNK) {
            int n = base + tid;
            x0s[tid] = x_c[2 * n + 0];
            x1s[tid] = x_c[2 * n + 1];
            ysh[tid] = y_c[n];
            tsh[tid] = t_c[n];
            msh[tid] = (mask[n] != 0) ? 0.0f : 1.0f;   // nonzero = drop point
        }
        __syncthreads();

        // ---- Phase A: build U, V, VY, VT (warp writes 32 consecutive g) ----
        {
            const int g  = tid & 63;
            const int i0 = tid >> 6;                       // 0..3
            const float cg = -1.0f + (float)g * (2.0f / 63.0f);
            #pragma unroll
            for (int j = i0; j < CHUNK; j += 4) {
                float dx = x0s[j] - cg;
                float dy = x1s[j] - cg;
                float u  = msh[j] * __expf(-50.0f * dx * dx);
                float v  = __expf(-50.0f * dy * dy);
                Ush [j * 64 + g] = u;
                Vsh [j * 64 + g] = v;
                VYsh[j * 64 + g] = v * ysh[j];
                VTsh[j * 64 + g] = v * tsh[j];
            }
        }
        __syncthreads();

        // ---- Phase B: pure FMA2 rank-1 accumulation ----
        #pragma unroll 4
        for (int n = 0; n < CHUNK; n++) {
            const int vo = n * 64 + gyg * 4;
            const ulonglong2 v2  = *reinterpret_cast<const ulonglong2*>(Vsh  + vo);
            const ulonglong2 vy2 = *reinterpret_cast<const ulonglong2*>(VYsh + vo);
            const ulonglong2 vt2 = *reinterpret_cast<const ulonglong2*>(VTsh + vo);
            const float4 u4 = *reinterpret_cast<const float4*>(Ush + n * 64 + gxg * 4);

            const unsigned long long vv[2] = { v2.x,  v2.y  };
            const unsigned long long vy[2] = { vy2.x, vy2.y };
            const unsigned long long vt[2] = { vt2.x, vt2.y };
            const float uarr[4] = { u4.x, u4.y, u4.z, u4.w };
            #pragma unroll
            for (int i = 0; i < 4; i++) {
                const unsigned long long us = splat2(uarr[i]);
                #pragma unroll
                for (int j = 0; j < 2; j++) {
                    FMA2(aD[i][j], us, vv[j]);
                    FMA2(aY[i][j], us, vy[j]);
                    FMA2(aT[i][j], us, vt[j]);
                }
            }
        }
    }

    // ---- store partial tile [b][part][c][gy*64+gx], coalesced STG.128 ----
    float* outp = g_partial + (size_t)(b * NPART + part) * 3 * GG;
    #pragma unroll
    for (int r = 0; r < 4; r++) {                 // gy row within tile
        const int j = r >> 1, hi = r & 1;
        float4 wD, wY, wT;
        float lo0, hi0;
        unpack2(aD[0][j], lo0, hi0); wD.x = hi ? hi0 : lo0;
        unpack2(aD[1][j], lo0, hi0); wD.y = hi ? hi0 : lo0;
        unpack2(aD[2][j], lo0, hi0); wD.z = hi ? hi0 : lo0;
        unpack2(aD[3][j], lo0, hi0); wD.w = hi ? hi0 : lo0;
        unpack2(aY[0][j], lo0, hi0); wY.x = hi ? hi0 : lo0;
        unpack2(aY[1][j], lo0, hi0); wY.y = hi ? hi0 : lo0;
        unpack2(aY[2][j], lo0, hi0); wY.z = hi ? hi0 : lo0;
        unpack2(aY[3][j], lo0, hi0); wY.w = hi ? hi0 : lo0;
        unpack2(aT[0][j], lo0, hi0); wT.x = hi ? hi0 : lo0;
        unpack2(aT[1][j], lo0, hi0); wT.y = hi ? hi0 : lo0;
        unpack2(aT[2][j], lo0, hi0); wT.z = hi ? hi0 : lo0;
        unpack2(aT[3][j], lo0, hi0); wT.w = hi ? hi0 : lo0;
        const int col = (gyg * 4 + r) * 64 + gxg * 4;
        *reinterpret_cast<float4*>(outp +          col) = wD;
        *reinterpret_cast<float4*>(outp + GG     + col) = wY;
        *reinterpret_cast<float4*>(outp + 2 * GG + col) = wT;
    }
}

// Kernel 2: reduce NPART partials, 8-way split-K across threads, normalize.
// grid 1024 blocks (8 b x 128 g-blocks of 32 g) x 256 threads (32 g x 8 splits).
__global__ __launch_bounds__(256)
void rbf_finalize_kernel(float* __restrict__ out)
{
    __shared__ float sD[256], s0[256], s1[256];

    const int b    = blockIdx.x >> 7;
    const int gblk = blockIdx.x & 127;
    const int tid  = threadIdx.x;
    const int gl   = tid & 31;          // g within block
    const int sp   = tid >> 5;          // split 0..7 -> 4 chunks each
    const int g    = gblk * 32 + gl;

    const float* p = g_partial + (size_t)b * NPART * 3 * GG;
    float d = 0.f, a0 = 0.f, a1 = 0.f;
    #pragma unroll
    for (int k = 0; k < NPART / 8; k++) {
        const float* q = p + (size_t)(sp * (NPART / 8) + k) * 3 * GG;
        d  += q[g];
        a0 += q[GG + g];
        a1 += q[2 * GG + g];
    }
    sD[tid] = d; s0[tid] = a0; s1[tid] = a1;
    __syncthreads();

    if (tid < 32) {
        float dd = 0.f, y = 0.f, t = 0.f;
        #pragma unroll
        for (int w = 0; w < 8; w++) {
            dd += sD[tid + 32 * w];
            y  += s0[tid + 32 * w];
            t  += s1[tid + 32 * w];
        }
        float inv = 1.0f / (dd + 1e-5f);
        float* o = out + (size_t)b * 3 * GG;
        o[g]          = dd;
        o[GG + g]     = y * inv;
        o[2 * GG + g] = t * inv;
    }
}

extern "C" void kernel_launch(void* const* d_in, const int* in_sizes, int n_in,
                              void* d_out, int out_size)
{
    const float* x_c  = (const float*)d_in[0];   // (8,4096,2) float32
    const float* y_c  = (const float*)d_in[1];   // (8,4096,1) float32
    const float* t_c  = (const float*)d_in[2];   // (8,4096,1) float32
    const int*   mask = (const int*)d_in[3];     // (8,4096) bool -> int32
    float* out = (float*)d_out;                  // (8,3,64,64) float32

    const int dyn_smem = 4 * CHUNK * 64 * sizeof(float);   // 64 KB
    static int attr_done = 0;
    if (!attr_done) {
        cudaFuncSetAttribute(rbf_partial_kernel,
                             cudaFuncAttributeMaxDynamicSharedMemorySize, dyn_smem);
        attr_done = 1;
    }

    dim3 grid1(NPART, NB);              // 32 x 8 = 256 blocks, 128 points each
    rbf_partial_kernel<<<grid1, 256, dyn_smem>>>(x_c, y_c, t_c, mask);

    rbf_finalize_kernel<<<NB * 128, 256>>>(out);  // 1024 blocks
}